// round 6
// baseline (speedup 1.0000x reference)
#include <cuda_runtime.h>
#include <cstdint>

#define D_IN   128
#define D_OUT  64
#define D_EDGE 11
#define NMAX   100000
#define EMAX   1000000
#define NEG_SLOPE 0.2f
#define SCAN_BLK 512

// Scratch: ONLY referenced from device code (host-side use of a __device__
// symbol passes the host shadow address; ATS silently dereferences it).
__device__ float g_xl[(size_t)NMAX * D_OUT];     // x @ W_l
__device__ float g_xr[(size_t)NMAX * D_OUT];     // x @ W_r
__device__ float4 g_ea16[(size_t)EMAX * 3];      // edge_attr padded to 48B rows
__device__ int2  g_sd[EMAX];                     // decoded (src, dst)
__device__ int2  g_csr[EMAX];                    // CSR payload: (src, eid)
__device__ int   g_cnt[NMAX];                    // in-degree counts
__device__ int   g_off[NMAX];                    // CSR offsets
__device__ int   g_cursor[NMAX];                 // scatter cursors
__device__ int   g_bsum[(NMAX + SCAN_BLK - 1) / SCAN_BLK]; // scan partials
__device__ int   g_is64;
__device__ int   g_diag;

// ---------------------------------------------------------------------------
__global__ void init_kernel(int n) {
    int stride = gridDim.x * blockDim.x;
    int tid0 = blockIdx.x * blockDim.x + threadIdx.x;
    if (tid0 == 0) g_diag = 0;
    for (int i = tid0; i < n; i += stride) g_cnt[i] = 0;
}

__global__ void set_diag_kernel(int bits) {
    if (threadIdx.x == 0) atomicOr(&g_diag, bits);
}

// Detect int32 vs int64 edge_index (int64 values < 2^31 -> hi words all zero).
__global__ void detect_kernel(const int* __restrict__ ei, int E) {
    if (threadIdx.x == 0) {
        int nz_hi = 0;
        int lim = (E > 64) ? 64 : E;
        for (int k = 0; k < lim; k++)
            if (ei[2 * k + 1] != 0) nz_hi++;
        g_is64 = (nz_hi == 0) ? 1 : 0;
    }
}

// Decode edge_index -> (src,dst) pairs + per-dst counts.
__global__ void decode_kernel(const int* __restrict__ ei, int E, int n) {
    const int is64 = g_is64;
    int stride = gridDim.x * blockDim.x;
    for (int i = blockIdx.x * blockDim.x + threadIdx.x; i < E; i += stride) {
        int s, d;
        if (is64) { s = ei[2 * i];  d = ei[2 * E + 2 * i]; }
        else      { s = ei[i];      d = ei[E + i]; }
        if ((unsigned)s >= (unsigned)n) { atomicOr(&g_diag, 4); s = 0; }
        if ((unsigned)d >= (unsigned)n) { atomicOr(&g_diag, 4); d = 0; }
        g_sd[i] = make_int2(s, d);
        atomicAdd(&g_cnt[d], 1);
    }
}

// Copy edge_attr [E,11] into 16B-aligned 12-float rows (coalesced).
__global__ void copy_ea_kernel(const float* __restrict__ ea, int E) {
    float* dst = reinterpret_cast<float*>(g_ea16);
    int total = E * D_EDGE;
    int stride = gridDim.x * blockDim.x;
    for (int i = blockIdx.x * blockDim.x + threadIdx.x; i < total; i += stride) {
        int e = i / D_EDGE, j = i - e * D_EDGE;
        dst[e * 12 + j] = ea[i];
    }
}

// ---- 3-kernel exclusive scan over g_cnt -> g_off ---------------------------
__global__ void scanA_kernel(int n) {
    __shared__ int s[SCAN_BLK];
    int t = threadIdx.x;
    int idx = blockIdx.x * SCAN_BLK + t;
    int v = (idx < n) ? g_cnt[idx] : 0;
    s[t] = v; __syncthreads();
    for (int off = 1; off < SCAN_BLK; off <<= 1) {
        int x = (t >= off) ? s[t - off] : 0;
        __syncthreads();
        s[t] += x;
        __syncthreads();
    }
    if (idx < n) g_off[idx] = s[t] - v;          // exclusive
    if (t == SCAN_BLK - 1) g_bsum[blockIdx.x] = s[t];
}

__global__ void scanB_kernel(int nblk) {
    if (threadIdx.x == 0) {
        int run = 0;
        for (int b = 0; b < nblk; b++) { int t = g_bsum[b]; g_bsum[b] = run; run += t; }
    }
}

__global__ void scanC_kernel(int n) {
    int idx = blockIdx.x * SCAN_BLK + threadIdx.x;
    if (idx < n) {
        int o = g_off[idx] + g_bsum[blockIdx.x];
        g_off[idx] = o;
        g_cursor[idx] = o;
    }
}

// Scatter edges into CSR buckets (integer atomics only).
__global__ void scatter_kernel(int E) {
    int stride = gridDim.x * blockDim.x;
    for (int i = blockIdx.x * blockDim.x + threadIdx.x; i < E; i += stride) {
        int2 sd = g_sd[i];
        int pos = atomicAdd(&g_cursor[sd.y], 1);
        g_csr[pos] = make_int2(sd.x, i);
    }
}

__global__ void diag_apply_kernel(float* __restrict__ out, int total) {
    const int diag = g_diag;
    if (diag == 0) return;
    float v = 0.f;
    if (diag & 4) v = 1e16f;
    if (diag & 8) v = 1e20f;
    int stride = gridDim.x * blockDim.x;
    for (int i = blockIdx.x * blockDim.x + threadIdx.x; i < total; i += stride)
        out[i] = v;
}

// ---------------------------------------------------------------------------
// GEMM (R4 baseline, measured 71.4us): g_x{l,r}[n,64] = x[n,128] @ W[128,64].
// ---------------------------------------------------------------------------
__global__ __launch_bounds__(256) void gemm_kernel(
    const float* __restrict__ x, const float* __restrict__ W,
    int n, int which)
{
    float* __restrict__ out = which ? g_xr : g_xl;   // device-side symbol

    __shared__ float sW[D_IN * D_OUT];  // 32 KB
    for (int i = threadIdx.x; i < D_IN * D_OUT / 4; i += 256) {
        reinterpret_cast<float4*>(sW)[i] = reinterpret_cast<const float4*>(W)[i];
    }
    __syncthreads();

    const int cg   = threadIdx.x & 7;
    const int rg   = threadIdx.x >> 3;
    const int row0 = blockIdx.x * 128 + rg * 4;

    float acc[4][8];
#pragma unroll
    for (int r = 0; r < 4; r++)
#pragma unroll
        for (int c = 0; c < 8; c++) acc[r][c] = 0.0f;

    for (int k = 0; k < D_IN; k += 4) {
        float xk[4][4];
#pragma unroll
        for (int r = 0; r < 4; r++) {
            int row = row0 + r;
            float4 v = make_float4(0.f, 0.f, 0.f, 0.f);
            if (row < n)
                v = *reinterpret_cast<const float4*>(x + (size_t)row * D_IN + k);
            xk[r][0] = v.x; xk[r][1] = v.y; xk[r][2] = v.z; xk[r][3] = v.w;
        }
#pragma unroll
        for (int kk = 0; kk < 4; kk++) {
            float4 w0 = *reinterpret_cast<const float4*>(&sW[(k + kk) * D_OUT + cg * 8]);
            float4 w1 = *reinterpret_cast<const float4*>(&sW[(k + kk) * D_OUT + cg * 8 + 4]);
#pragma unroll
            for (int r = 0; r < 4; r++) {
                float xv = xk[r][kk];
                acc[r][0] += xv * w0.x;  acc[r][1] += xv * w0.y;
                acc[r][2] += xv * w0.z;  acc[r][3] += xv * w0.w;
                acc[r][4] += xv * w1.x;  acc[r][5] += xv * w1.y;
                acc[r][6] += xv * w1.z;  acc[r][7] += xv * w1.w;
            }
        }
    }

#pragma unroll
    for (int r = 0; r < 4; r++) {
        int row = row0 + r;
        if (row < n) {
            float4* p = reinterpret_cast<float4*>(out + (size_t)row * D_OUT + cg * 8);
            p[0] = make_float4(acc[r][0], acc[r][1], acc[r][2], acc[r][3]);
            p[1] = make_float4(acc[r][4], acc[r][5], acc[r][6], acc[r][7]);
        }
    }
}

// ---------------------------------------------------------------------------
// Node kernel: warp per dst node, lane owns output cols (2*lane, 2*lane+1).
// Gathers all incoming edges from CSR; NO floating-point atomics anywhere.
//   per edge:  ec   = attr @ We            (the lsum term accumulates as eacc)
//              logit= lrelu(xl[src]+xr[i]+ec) . att   (5-shfl reduce)
//              ex   = exp(logit)           (max-free softmax, |logit| small)
//              acc += ex*xl[src]; den += ex; eacc += ec
//   self-loop: el = eacc/max(deg,1); same logit path with xl[i]
//   out[i] = (acc + ex_s*xl[i]) / (den + ex_s)
// ---------------------------------------------------------------------------
__global__ __launch_bounds__(256) void node_kernel(
    const float* __restrict__ We, const float* __restrict__ att,
    float* __restrict__ out, int n)
{
    const int lane = threadIdx.x & 31;
    const int node = (blockIdx.x * blockDim.x + threadIdx.x) >> 5;
    if (node >= n) return;

    // Per-lane 2-column slice of W_e and att, in registers.
    float we0[D_EDGE], we1[D_EDGE];
#pragma unroll
    for (int j = 0; j < D_EDGE; j++) {
        float2 w = *reinterpret_cast<const float2*>(We + j * D_OUT + 2 * lane);
        we0[j] = w.x; we1[j] = w.y;
    }
    const float2 at = *reinterpret_cast<const float2*>(att + 2 * lane);

    const float2 vr = *reinterpret_cast<const float2*>(g_xr + (size_t)node * D_OUT + 2 * lane);
    const float2 vli = *reinterpret_cast<const float2*>(g_xl + (size_t)node * D_OUT + 2 * lane);

    const int start = g_off[node];
    const int deg   = g_cnt[node];

    float acc0 = 0.f, acc1 = 0.f, den = 0.f, ea0 = 0.f, ea1 = 0.f;

    for (int k = 0; k < deg; k++) {
        const int2 ce = g_csr[start + k];          // (src, eid): uniform LDG.64
        const float4* ap = g_ea16 + (size_t)ce.y * 3;
        const float4 q0 = __ldg(ap);               // attr[0..3]
        const float4 q1 = __ldg(ap + 1);           // attr[4..7]
        const float4 q2 = __ldg(ap + 2);           // attr[8..10] (+pad)
        const float2 vl = *reinterpret_cast<const float2*>(
            g_xl + (size_t)ce.x * D_OUT + 2 * lane);

        float e0 = q0.x * we0[0] + q0.y * we0[1] + q0.z * we0[2] + q0.w * we0[3]
                 + q1.x * we0[4] + q1.y * we0[5] + q1.z * we0[6] + q1.w * we0[7]
                 + q2.x * we0[8] + q2.y * we0[9] + q2.z * we0[10];
        float e1 = q0.x * we1[0] + q0.y * we1[1] + q0.z * we1[2] + q0.w * we1[3]
                 + q1.x * we1[4] + q1.y * we1[5] + q1.z * we1[6] + q1.w * we1[7]
                 + q2.x * we1[8] + q2.y * we1[9] + q2.z * we1[10];

        float m0 = vl.x + vr.x + e0;
        float m1 = vl.y + vr.y + e1;
        m0 = (m0 >= 0.f) ? m0 : NEG_SLOPE * m0;
        m1 = (m1 >= 0.f) ? m1 : NEG_SLOPE * m1;
        float p = m0 * at.x + m1 * at.y;
#pragma unroll
        for (int o = 16; o > 0; o >>= 1)
            p += __shfl_xor_sync(0xffffffffu, p, o);
        const float ex = __expf(p);

        acc0 += ex * vl.x;
        acc1 += ex * vl.y;
        den  += ex;
        ea0  += e0;
        ea1  += e1;
    }

    // Self-loop: loop_attr@We = eacc/max(deg,1)
    const float inv_deg = 1.0f / fmaxf((float)deg, 1.0f);
    float m0 = vli.x + vr.x + ea0 * inv_deg;
    float m1 = vli.y + vr.y + ea1 * inv_deg;
    m0 = (m0 >= 0.f) ? m0 : NEG_SLOPE * m0;
    m1 = (m1 >= 0.f) ? m1 : NEG_SLOPE * m1;
    float p = m0 * at.x + m1 * at.y;
#pragma unroll
    for (int o = 16; o > 0; o >>= 1)
        p += __shfl_xor_sync(0xffffffffu, p, o);
    const float exs = __expf(p);

    const float invd = 1.0f / (den + exs);
    float2 o;
    o.x = (acc0 + exs * vli.x) * invd;
    o.y = (acc1 + exs * vli.y) * invd;
    *reinterpret_cast<float2*>(out + (size_t)node * D_OUT + 2 * lane) = o;
}

// ---------------------------------------------------------------------------
extern "C" void kernel_launch(void* const* d_in, const int* in_sizes, int n_in,
                              void* d_out, int out_size)
{
    const float *x = nullptr, *ea = nullptr, *Wl = nullptr, *Wr = nullptr;
    const float *We = nullptr, *att = nullptr;
    const int   *ei = nullptr;
    long long E = 0;
    int n = 0;

    for (int i = 0; i < n_in; i++) {               // pass 1: edge_attr
        long long s = in_sizes[i];
        if (s > 100000 && s % D_EDGE == 0) { ea = (const float*)d_in[i]; E = s / D_EDGE; }
    }
    for (int i = 0; i < n_in; i++) {               // pass 2: everything else
        long long s = in_sizes[i];
        const void* p = d_in[i];
        if (p == (const void*)ea) continue;
        if      (E > 0 && (s == 2 * E || s == 4 * E)) { ei = (const int*)p; }
        else if (s == D_IN * D_OUT)   { if (!Wl) Wl = (const float*)p; else Wr = (const float*)p; }
        else if (s == D_EDGE * D_OUT) { We  = (const float*)p; }
        else if (s == D_OUT)          { att = (const float*)p; }
        else if (s > 100000 && s % D_IN == 0) { x = (const float*)p; n = (int)(s / D_IN); }
    }

    float* out = (float*)d_out;
    const int total_out = out_size;

    if (!x || !ea || !ei || !Wl || !Wr || !We || !att || n <= 0 || E <= 0 ||
        n > NMAX || E > EMAX) {
        set_diag_kernel<<<1, 32>>>(8);
        diag_apply_kernel<<<512, 256>>>(out, total_out);
        return;
    }
    const int Ei = (int)E;
    const int nblk = (n + SCAN_BLK - 1) / SCAN_BLK;

    init_kernel<<<256, 256>>>(n);
    detect_kernel<<<1, 32>>>(ei, Ei);
    decode_kernel<<<512, 256>>>(ei, Ei, n);
    copy_ea_kernel<<<2048, 256>>>(ea, Ei);

    scanA_kernel<<<nblk, SCAN_BLK>>>(n);
    scanB_kernel<<<1, 32>>>(nblk);
    scanC_kernel<<<nblk, SCAN_BLK>>>(n);
    scatter_kernel<<<512, 256>>>(Ei);

    gemm_kernel<<<(n + 127) / 128, 256>>>(x, Wl, n, 0);  // -> g_xl
    gemm_kernel<<<(n + 127) / 128, 256>>>(x, Wr, n, 1);  // -> g_xr

    node_kernel<<<(n * 32 + 255) / 256, 256>>>(We, att, out, n);

    diag_apply_kernel<<<512, 256>>>(out, total_out);
}